// round 16
// baseline (speedup 1.0000x reference)
#include <cuda_runtime.h>
#include <cuda_fp16.h>
#include <cuda_bf16.h>
#include <cstdint>

// ---------------- problem dims ----------------
#define B_SZ   1024
#define S_SZ   256
#define IN_SZ  8
#define H_SZ   512
#define F_SZ   96
#define G4     2048          // 4*H
#define KV     512           // single-pass fp16: A = [Ah], B = [Wh]
#define NCHUNK 4             // KV / 128
#define NCTA_N 16
#define NCTA_M 8
#define NSTEPS (S_SZ + F_SZ) // 352: t=256 is decoder step 0 (td=0) .. t=351 (td=95)

// ---------------- shared memory layout (persistent) ----------------
// 3 stages x 64 KB (A-sub0 16K | A-sub1 16K | B-sub0 16K | B-sub1 16K)
// epilogue reuses stage-0/1 area as C (128x132 f32 = 67.6 KB); c-state tile is persistent.
#define ST_BYTES  65536
#define SM_BIAS   196608   // 128 floats
#define SM_WIH    197120   // 128*8 floats
#define SM_XS     201216   // 128*9 floats
#define SM_OUTW   205824   // 32 floats
#define SM_CST    205952   // 128*32 floats (cell state, persistent across steps)
#define SMEM_TOTAL 222336

// ---------------- static device scratch (no runtime alloc) ----------------
__device__ __align__(1024) __half g_Wv[3][(size_t)G4 * KV];   // enc / dec0 / dec-folded
__device__ __align__(1024) __half g_A[2][(size_t)B_SZ * KV];  // ping-pong h (fp16)
__device__ float g_bias[3][G4];                               // permuted fused biases
__device__ float g_WihP[G4 * IN_SZ];                          // permuted enc_Wih
__device__ float g_predP[F_SZ][NCTA_N][B_SZ];                 // per-nCTA pred partials
__device__ int   g_bar;                                       // grid barrier counter

// ---------------- helpers ----------------
__device__ __forceinline__ uint32_t smem_u32(const void* p) {
    uint32_t a;
    asm("{ .reg .u64 t; cvta.to.shared.u64 t, %1; cvt.u32.u64 %0, t; }" : "=r"(a) : "l"(p));
    return a;
}
__device__ __forceinline__ void cp16(uint32_t saddr, const void* gptr) {
    asm volatile("cp.async.cg.shared.global [%0], [%1], 16;"
                 :: "r"(saddr), "l"(__cvta_generic_to_global(gptr)) : "memory");
}
#define CP_COMMIT() asm volatile("cp.async.commit_group;" ::: "memory")
#define CP_WAIT1()  asm volatile("cp.async.wait_group 1;" ::: "memory")
#define CP_WAIT0()  asm volatile("cp.async.wait_group 0;" ::: "memory")

__device__ __forceinline__ void ldm4(uint32_t& r0, uint32_t& r1, uint32_t& r2, uint32_t& r3,
                                     uint32_t addr) {
    asm volatile("ldmatrix.sync.aligned.m8n8.x4.shared.b16 {%0,%1,%2,%3}, [%4];"
                 : "=r"(r0), "=r"(r1), "=r"(r2), "=r"(r3) : "r"(addr));
}
__device__ __forceinline__ void mma16816(float* c, const uint32_t* a, const uint32_t* b) {
    asm volatile(
        "mma.sync.aligned.m16n8k16.row.col.f32.f16.f16.f32 "
        "{%0,%1,%2,%3}, {%4,%5,%6,%7}, {%8,%9}, {%0,%1,%2,%3};"
        : "+f"(c[0]), "+f"(c[1]), "+f"(c[2]), "+f"(c[3])
        : "r"(a[0]), "r"(a[1]), "r"(a[2]), "r"(a[3]), "r"(b[0]), "r"(b[1]));
}

// fast activations: hardware EX2/RCP. Error ~2^-21 (far below fp16 h-quant 2^-11).
__device__ __forceinline__ float fsig(float x) {
    x = fminf(fmaxf(x, -30.f), 30.f);
    return __fdividef(1.f, 1.f + __expf(-x));
}
__device__ __forceinline__ float ftanh(float x) {
    x = fminf(fmaxf(x, -15.f), 15.f);
    float e = __expf(2.f * x);
    return __fdividef(e - 1.f, e + 1.f);
}

// ---------------- prep: permute weights to fp16, fold decoder feedback ----------------
// permuted col p = 4u + gate  <-  source row s = gate*512 + u  (PyTorch gate order i,f,g,o)
__global__ void prep_kernel(const float* __restrict__ encWhh, const float* __restrict__ decWhh,
                            const float* __restrict__ decWih, const float* __restrict__ outW,
                            const float* __restrict__ encBih, const float* __restrict__ encBhh,
                            const float* __restrict__ decBih, const float* __restrict__ decBhh,
                            const float* __restrict__ outB,   const float* __restrict__ encWih) {
    int idx = blockIdx.x * blockDim.x + threadIdx.x;
    if (idx < G4 * H_SZ) {
        int p = idx >> 9;
        int k = idx & 511;
        int s = ((p & 3) << 9) | (p >> 2);
        size_t o = (size_t)p * KV + k;

        g_Wv[0][o] = __float2half_rn(encWhh[s * H_SZ + k]);
        float v1 = decWhh[s * H_SZ + k];
        g_Wv[1][o] = __float2half_rn(v1);
        g_Wv[2][o] = __float2half_rn(v1 + decWih[s] * outW[k]);   // fold y-feedback
    }
    if (idx < G4) {
        int p = idx;
        int s = ((p & 3) << 9) | (p >> 2);
        g_bias[0][p] = encBih[s] + encBhh[s];
        float db = decBih[s] + decBhh[s];
        g_bias[1][p] = db;
        g_bias[2][p] = db + outB[0] * decWih[s];       // fold outB feedback
#pragma unroll
        for (int j = 0; j < IN_SZ; j++) g_WihP[p * IN_SZ + j] = encWih[s * IN_SZ + j];
    }
}

__global__ void init_kernel() {
    int i = blockIdx.x * blockDim.x + threadIdx.x;
    int stride = gridDim.x * blockDim.x;
    if (i == 0) g_bar = 0;                             // reset barrier every launch/replay
    uint32_t* a0 = reinterpret_cast<uint32_t*>(g_A[0]);
    for (int idx = i; idx < B_SZ * KV / 2; idx += stride) a0[idx] = 0u;
}

// ---------------- persistent kernel: all 352 LSTM steps ----------------
// grid (16, 8) = 128 CTAs, 1 CTA/SM (222 KB smem) => all co-resident, barrier is safe.
// Per step: C[128x128] = A[1024x512] x B[2048x512]^T, gate math locally; c-state lives
// in smem (CTA-private across steps). Barrier latency hidden behind next-step B loads.
__global__ void __launch_bounds__(512, 1)
persist_kernel(const float* __restrict__ x, const float* __restrict__ outW) {
    extern __shared__ char smem[];
    const uint32_t sb = smem_u32(smem);
    const int tid = threadIdx.x;
    const int n0 = blockIdx.x, m0 = blockIdx.y;

    float* sm_bias = (float*)(smem + SM_BIAS);
    float* sm_wih  = (float*)(smem + SM_WIH);
    float* sm_xs   = (float*)(smem + SM_XS);
    float* sm_outw = (float*)(smem + SM_OUTW);
    float* smC     = (float*)(smem + SM_CST);

    const int lane = tid & 31, w = tid >> 5;
    const int wk = w & 1;                 // K-half of each chunk (4 k16-slices each)
    const int wn = (w >> 1) & 3;          // 4 n-columns of 32
    const int wm = w >> 3;                // 2 m-rows of 64
    const int lrow = lane & 15, lhalf = lane >> 4;

    // step-invariant consts + zero c-state
    if (tid < 32) sm_outw[tid] = outW[n0 * 32 + tid];
    for (int i = tid; i < 128 * IN_SZ; i += 512) sm_wih[i] = g_WihP[n0 * 128 * IN_SZ + i];
    for (int i = tid; i < 128 * 32; i += 512) smC[i] = 0.f;

    // loaders: B half (st+32K..64K), A half (st+0..32K); 64-B-row swizzled sub-blocks
    auto load_B = [&](const __half* gB, int kc, int slot) {
        const uint32_t st = sb + slot * ST_BYTES + 32768;
        const int c16 = tid & 7, rb = tid >> 3;
#pragma unroll
        for (int sub = 0; sub < 2; sub++) {
            const int kofs = kc * 128 + sub * 64;
#pragma unroll
            for (int it = 0; it < 2; it++) {
                int r = rb + it * 64;
                uint32_t so = (uint32_t)(r * 128 + ((c16 ^ (r & 7)) << 4));
                cp16(st + sub * 16384 + so, gB + (size_t)r * KV + kofs + c16 * 8);
            }
        }
    };
    auto load_A = [&](const __half* gA, int kc, int slot) {
        const uint32_t st = sb + slot * ST_BYTES;
        const int c16 = tid & 7, rb = tid >> 3;
#pragma unroll
        for (int sub = 0; sub < 2; sub++) {
            const int kofs = kc * 128 + sub * 64;
#pragma unroll
            for (int it = 0; it < 2; it++) {
                int r = rb + it * 64;
                uint32_t so = (uint32_t)(r * 128 + ((c16 ^ (r & 7)) << 4));
                cp16(st + sub * 16384 + so, gA + (size_t)r * KV + kofs + c16 * 8);
            }
        }
    };

    // step-0 prologue (same group structure as the in-loop prefetch: Gb0,Gb1,Ga0,Ga1)
    const __half* gA = g_A[0] + (size_t)m0 * 128 * KV;
    const __half* gB = g_Wv[0] + (size_t)n0 * 128 * KV;
    if (tid < 128) sm_bias[tid] = g_bias[0][n0 * 128 + tid];
    for (int i = tid; i < 128 * IN_SZ; i += 512) {
        int r = i >> 3, j = i & 7;
        sm_xs[r * 9 + j] = x[((size_t)(m0 * 128 + r) * S_SZ + 0) * IN_SZ + j];
    }
    load_B(gB, 0, 0); CP_COMMIT();
    load_B(gB, 1, 1); CP_COMMIT();
    load_A(gA, 0, 0); CP_COMMIT();
    load_A(gA, 1, 1); CP_COMMIT();
    __syncthreads();   // consts + smC visible

    for (int t = 0; t < NSTEPS; t++) {
        const bool has_x = (t < S_SZ);
        const int td = (t >= S_SZ) ? (t - S_SZ) : -1;   // 0..95

        float acc[4][4][4];
#pragma unroll
        for (int a = 0; a < 4; a++)
#pragma unroll
            for (int b = 0; b < 4; b++)
#pragma unroll
                for (int c = 0; c < 4; c++) acc[a][b][c] = 0.f;

        // ---- mainloop: 4 chunks of K=128, slots {0,1,2,0}, waits {1,1,1,0} ----
#pragma unroll
        for (int kc = 0; kc < NCHUNK; kc++) {
            if (kc < 3) { CP_WAIT1(); } else { CP_WAIT0(); }
            __syncthreads();
            const int slot = (kc == 3) ? 0 : kc;
            const uint32_t st = sb + slot * ST_BYTES;
#pragma unroll
            for (int j = 0; j < 4; j++) {
                const int s_g  = wk * 4 + j;          // k16-slice 0..7 within chunk
                const int sub  = s_g >> 2;
                const int c16  = 2 * (s_g & 3) + lhalf;
                const uint32_t stA = st + sub * 16384;
                const uint32_t stB = st + 32768 + sub * 16384;
                uint32_t af[4][4];
#pragma unroll
                for (int mt = 0; mt < 4; mt++) {
                    int r = wm * 64 + mt * 16 + lrow;
                    ldm4(af[mt][0], af[mt][1], af[mt][2], af[mt][3],
                         stA + r * 128 + ((c16 ^ (r & 7)) << 4));
                }
                uint32_t bfr[4][2];
#pragma unroll
                for (int nb = 0; nb < 2; nb++) {
                    int r = wn * 32 + nb * 16 + lrow;
                    uint32_t r0, r1, r2, r3;
                    ldm4(r0, r1, r2, r3, stB + r * 128 + ((c16 ^ (r & 7)) << 4));
                    bfr[nb * 2 + 0][0] = r0; bfr[nb * 2 + 0][1] = r2;
                    bfr[nb * 2 + 1][0] = r1; bfr[nb * 2 + 1][1] = r3;
                }
#pragma unroll
                for (int mt = 0; mt < 4; mt++)
#pragma unroll
                    for (int nt = 0; nt < 4; nt++)
                        mma16816(acc[mt][nt], af[mt], bfr[nt]);
            }
            __syncthreads();
            if (kc == 0) { load_A(gA, 2, 2); load_B(gB, 2, 2); CP_COMMIT(); }
            else if (kc == 1) { load_A(gA, 3, 0); load_B(gB, 3, 0); CP_COMMIT(); }
        }

        // ---- spill + K-half reduction into smem C tile (sb+0, stride 132) ----
        float* Cs = reinterpret_cast<float*>(smem);
        if (wk == 0) {
#pragma unroll
            for (int mt = 0; mt < 4; mt++) {
#pragma unroll
                for (int nt = 0; nt < 4; nt++) {
                    int r = wm * 64 + mt * 16 + (lane >> 2);
                    int c = wn * 32 + nt * 8 + 2 * (lane & 3);
                    Cs[r * 132 + c]           = acc[mt][nt][0];
                    Cs[r * 132 + c + 1]       = acc[mt][nt][1];
                    Cs[(r + 8) * 132 + c]     = acc[mt][nt][2];
                    Cs[(r + 8) * 132 + c + 1] = acc[mt][nt][3];
                }
            }
        }
        __syncthreads();
        if (wk == 1) {
#pragma unroll
            for (int mt = 0; mt < 4; mt++) {
#pragma unroll
                for (int nt = 0; nt < 4; nt++) {
                    int r = wm * 64 + mt * 16 + (lane >> 2);
                    int c = wn * 32 + nt * 8 + 2 * (lane & 3);
                    float2* p0 = reinterpret_cast<float2*>(&Cs[r * 132 + c]);
                    float2 v0 = *p0; v0.x += acc[mt][nt][0]; v0.y += acc[mt][nt][1]; *p0 = v0;
                    float2* p1 = reinterpret_cast<float2*>(&Cs[(r + 8) * 132 + c]);
                    float2 v1 = *p1; v1.x += acc[mt][nt][2]; v1.y += acc[mt][nt][3]; *p1 = v1;
                }
            }
        }
        __syncthreads();

        // ---- gate pass: lane = local unit, 16 warps x 8 rows; c-state in smem ----
        const int u = lane;
        const int ug = n0 * 32 + u;
        float wih[4][8];
        if (has_x) {
#pragma unroll
            for (int q = 0; q < 4; q++)
#pragma unroll
                for (int k = 0; k < 8; k++) wih[q][k] = sm_wih[(4 * u + q) * 8 + k];
        }
        const float b_i = sm_bias[4 * u], b_f = sm_bias[4 * u + 1];
        const float b_g = sm_bias[4 * u + 2], b_o = sm_bias[4 * u + 3];
        const float ow = sm_outw[u];
        __half* __restrict__ hout = g_A[(t & 1) ^ 1];

#pragma unroll 4
        for (int i = 0; i < 8; i++) {
            int r = w + i * 16;
            int grow = m0 * 128 + r;
            const float4 g4v = *reinterpret_cast<const float4*>(&Cs[r * 132 + 4 * u]);
            float gi = g4v.x + b_i, gf = g4v.y + b_f, gg = g4v.z + b_g, go = g4v.w + b_o;
            if (has_x) {
#pragma unroll
                for (int k = 0; k < 8; k++) {
                    float xv = sm_xs[r * 9 + k];
                    gi += xv * wih[0][k]; gf += xv * wih[1][k];
                    gg += xv * wih[2][k]; go += xv * wih[3][k];
                }
            }
            float iv = fsig(gi);
            float fv = fsig(gf);
            float gv = ftanh(gg);
            float ov = fsig(go);
            float cn = fv * smC[r * 32 + u] + iv * gv;
            smC[r * 32 + u] = cn;
            float hv = ov * ftanh(cn);
            hout[(size_t)grow * KV + ug] = __float2half_rn(hv);
            if (td >= 0) {
                float p = hv * ow;
#pragma unroll
                for (int s = 16; s > 0; s >>= 1) p += __shfl_xor_sync(0xFFFFFFFFu, p, s);
                if (lane == 0) g_predP[td][n0][grow] = p;   // deterministic partial
            }
        }

        // ---- inter-step: prefetch next-step B/consts, hide barrier, then load A ----
        if (t + 1 < NSTEPS) {
            __syncthreads();   // C / sm_xs / sm_bias reads done; smC writes done
            const int t2 = t + 1;
            const int wsel2 = (t2 < S_SZ) ? 0 : (t2 == S_SZ ? 1 : 2);
            gB = g_Wv[wsel2] + (size_t)n0 * 128 * KV;
            gA = g_A[t2 & 1] + (size_t)m0 * 128 * KV;
            if (tid < 128) sm_bias[tid] = g_bias[wsel2][n0 * 128 + tid];
            if (t2 < S_SZ) {
                for (int i = tid; i < 128 * IN_SZ; i += 512) {
                    int r = i >> 3, j = i & 7;
                    sm_xs[r * 9 + j] = x[((size_t)(m0 * 128 + r) * S_SZ + t2) * IN_SZ + j];
                }
            }
            load_B(gB, 0, 0); CP_COMMIT();     // B doesn't depend on peer h-writes
            load_B(gB, 1, 1); CP_COMMIT();
            __threadfence();                   // release this CTA's h-writes
            __syncthreads();
            if (tid == 0) {
                atomicAdd(&g_bar, 1);
                const int target = NCTA_N * NCTA_M * (t + 1);
                while (*(volatile int*)&g_bar < target) __nanosleep(64);
            }
            __syncthreads();
            __threadfence();                   // acquire peers' h-writes
            load_A(gA, 0, 0); CP_COMMIT();
            load_A(gA, 1, 1); CP_COMMIT();
        }
    }
}

// ---------------- output: out[b][f] = outB + sum_n predP[f][n][b] ----------------
__global__ void out_kernel(float* __restrict__ out, const float* __restrict__ outB) {
    int i = blockIdx.x * blockDim.x + threadIdx.x;
    if (i < B_SZ * F_SZ) {
        int b = i / F_SZ, f = i % F_SZ;
        float s = outB[0];
#pragma unroll
        for (int n = 0; n < NCTA_N; n++) s += g_predP[f][n][b];
        out[i] = s;
    }
}

// ---------------- launch ----------------
extern "C" void kernel_launch(void* const* d_in, const int* in_sizes, int n_in,
                              void* d_out, int out_size) {
    const float* x      = (const float*)d_in[0];
    const float* encWih = (const float*)d_in[1];
    const float* encWhh = (const float*)d_in[2];
    const float* encBih = (const float*)d_in[3];
    const float* encBhh = (const float*)d_in[4];
    const float* decWih = (const float*)d_in[5];
    const float* decWhh = (const float*)d_in[6];
    const float* decBih = (const float*)d_in[7];
    const float* decBhh = (const float*)d_in[8];
    const float* outW   = (const float*)d_in[9];
    const float* outB   = (const float*)d_in[10];

    cudaFuncSetAttribute(persist_kernel, cudaFuncAttributeMaxDynamicSharedMemorySize, SMEM_TOTAL);

    init_kernel<<<512, 256>>>();
    prep_kernel<<<(G4 * H_SZ + 255) / 256, 256>>>(encWhh, decWhh, decWih, outW,
                                                  encBih, encBhh, decBih, decBhh, outB, encWih);
    persist_kernel<<<dim3(NCTA_N, NCTA_M), 512, SMEM_TOTAL>>>(x, outW);
    out_kernel<<<(B_SZ * F_SZ + 255) / 256, 256>>>((float*)d_out, outB);
}